// round 2
// baseline (speedup 1.0000x reference)
#include <cuda_runtime.h>

#define N_NODES 200000
#define N_EDGES 800000
#define D 128

// Scratch for the scatter-add aggregation (allocation-free rule: __device__ global).
__device__ float g_agg[(size_t)N_NODES * D];

// ---------------------------------------------------------------------------
// Kernel 1: zero the aggregation buffer (vectorized).
// ---------------------------------------------------------------------------
__global__ void zero_agg_kernel() {
    size_t i = (size_t)blockIdx.x * blockDim.x + threadIdx.x;
    size_t n = (size_t)N_NODES * D / 4;
    if (i < n) {
        ((float4*)g_agg)[i] = make_float4(0.f, 0.f, 0.f, 0.f);
    }
}

// ---------------------------------------------------------------------------
// Kernel 2: scatter-add edge_attr rows onto receiver nodes.
// One thread per (edge, 4-element group): float4 load + 4 scalar atomicAdds.
// edge_index is int32 (JAX x64-disabled downgrades int64 -> int32).
// ---------------------------------------------------------------------------
__global__ void scatter_kernel(const float* __restrict__ edge_attr,
                               const int* __restrict__ recv) {
    unsigned idx = blockIdx.x * blockDim.x + threadIdx.x;
    if (idx >= (unsigned)N_EDGES * 32u) return;
    unsigned e = idx >> 5;
    unsigned q = idx & 31u;
    int r = __ldg(recv + e);
    float4 v = ((const float4*)edge_attr)[(size_t)e * 32 + q];
    float* dst = g_agg + (size_t)r * D + (size_t)q * 4;
    atomicAdd(dst + 0, v.x);
    atomicAdd(dst + 1, v.y);
    atomicAdd(dst + 2, v.z);
    atomicAdd(dst + 3, v.w);
}

// ---------------------------------------------------------------------------
// Kernel 3: fused MLP.
//   h   = relu([x | agg] @ W1 + b1)   (K = 256)
//   out = h @ W2 + b2                 (K = 128)
//
// 256 threads per CTA, 64 nodes per tile (200000 = 3125 * 64 exactly).
// Thread (tx = lane 0..31, ty = warp 0..7) owns an 8-node x 4-col micro-tile.
// Shared (dynamic, 192 KB):
//   sW2  : 128x128 fp32 (resident whole kernel)
//   sW1c : 64x128 fp32  (K-chunk of W1, 4 chunks)
//   sA   : 64x256 fp32  (input tile: x ++ agg)
//   sH   : 64x128 fp32  (hidden tile)
// ---------------------------------------------------------------------------
__global__ __launch_bounds__(256) void mlp_kernel(
    const float* __restrict__ x,
    const float* __restrict__ W1,
    const float* __restrict__ b1,
    const float* __restrict__ W2,
    const float* __restrict__ b2,
    float* __restrict__ out) {

    extern __shared__ float smem[];
    float4* sW2  = (float4*)smem;       // 4096 float4 (64 KB)
    float4* sW1c = sW2  + 4096;         // 2048 float4 (32 KB)
    float4* sA   = sW1c + 2048;         // 4096 float4 (64 KB)
    float4* sH   = sA   + 4096;         // 2048 float4 (32 KB)

    const int tid = threadIdx.x;
    const int tx = tid & 31;    // column group: cols [4*tx, 4*tx+4)
    const int ty = tid >> 5;    // node group:   rows [8*ty, 8*ty+8)
    const int node0 = blockIdx.x * 64;

    // Load W2 (resident).
    const float4* W2g = (const float4*)W2;
    #pragma unroll
    for (int i = tid; i < 4096; i += 256) sW2[i] = W2g[i];

    // Load A tile: per node, k[0:128) = x, k[128:256) = agg. Row = 64 float4.
    #pragma unroll
    for (int i = tid; i < 64 * 64; i += 256) {
        int m = i >> 6;
        int f = i & 63;
        size_t node = (size_t)(node0 + m);
        float4 v = (f < 32) ? ((const float4*)x)[node * 32 + f]
                            : ((const float4*)g_agg)[node * 32 + (f - 32)];
        sA[m * 64 + f] = v;
    }

    float acc[8][4];
    #pragma unroll
    for (int m = 0; m < 8; ++m)
        #pragma unroll
        for (int c = 0; c < 4; ++c) acc[m][c] = 0.f;

    // ------------------- GEMM1: [64x256] @ [256x128] -------------------
    for (int kc = 0; kc < 4; ++kc) {
        const float4* W1g = (const float4*)(W1 + (size_t)kc * 64 * 128);
        #pragma unroll
        for (int i = tid; i < 2048; i += 256) sW1c[i] = W1g[i];
        __syncthreads();   // also orders sA/sW2 loads on first iteration

        #pragma unroll 4
        for (int kk = 0; kk < 64; kk += 4) {
            float4 w0 = sW1c[(kk + 0) * 32 + tx];
            float4 w1 = sW1c[(kk + 1) * 32 + tx];
            float4 w2 = sW1c[(kk + 2) * 32 + tx];
            float4 w3 = sW1c[(kk + 3) * 32 + tx];
            #pragma unroll
            for (int m = 0; m < 8; ++m) {
                float4 a = sA[(ty * 8 + m) * 64 + kc * 16 + (kk >> 2)];
                acc[m][0] += a.x * w0.x; acc[m][0] += a.y * w1.x;
                acc[m][0] += a.z * w2.x; acc[m][0] += a.w * w3.x;
                acc[m][1] += a.x * w0.y; acc[m][1] += a.y * w1.y;
                acc[m][1] += a.z * w2.y; acc[m][1] += a.w * w3.y;
                acc[m][2] += a.x * w0.z; acc[m][2] += a.y * w1.z;
                acc[m][2] += a.z * w2.z; acc[m][2] += a.w * w3.z;
                acc[m][3] += a.x * w0.w; acc[m][3] += a.y * w1.w;
                acc[m][3] += a.z * w2.w; acc[m][3] += a.w * w3.w;
            }
        }
        __syncthreads();
    }

    // bias + ReLU -> sH
    {
        float4 b1v = ((const float4*)b1)[tx];
        #pragma unroll
        for (int m = 0; m < 8; ++m) {
            float4 h;
            h.x = fmaxf(acc[m][0] + b1v.x, 0.f);
            h.y = fmaxf(acc[m][1] + b1v.y, 0.f);
            h.z = fmaxf(acc[m][2] + b1v.z, 0.f);
            h.w = fmaxf(acc[m][3] + b1v.w, 0.f);
            sH[(ty * 8 + m) * 32 + tx] = h;
            acc[m][0] = 0.f; acc[m][1] = 0.f; acc[m][2] = 0.f; acc[m][3] = 0.f;
        }
    }
    __syncthreads();

    // ------------------- GEMM2: [64x128] @ [128x128] -------------------
    #pragma unroll 4
    for (int kk = 0; kk < 128; kk += 4) {
        float4 w0 = sW2[(kk + 0) * 32 + tx];
        float4 w1 = sW2[(kk + 1) * 32 + tx];
        float4 w2 = sW2[(kk + 2) * 32 + tx];
        float4 w3 = sW2[(kk + 3) * 32 + tx];
        #pragma unroll
        for (int m = 0; m < 8; ++m) {
            float4 a = sH[(ty * 8 + m) * 32 + (kk >> 2)];
            acc[m][0] += a.x * w0.x; acc[m][0] += a.y * w1.x;
            acc[m][0] += a.z * w2.x; acc[m][0] += a.w * w3.x;
            acc[m][1] += a.x * w0.y; acc[m][1] += a.y * w1.y;
            acc[m][1] += a.z * w2.y; acc[m][1] += a.w * w3.y;
            acc[m][2] += a.x * w0.z; acc[m][2] += a.y * w1.z;
            acc[m][2] += a.z * w2.z; acc[m][2] += a.w * w3.z;
            acc[m][3] += a.x * w0.w; acc[m][3] += a.y * w1.w;
            acc[m][3] += a.z * w2.w; acc[m][3] += a.w * w3.w;
        }
    }

    // bias + store
    {
        float4 b2v = ((const float4*)b2)[tx];
        #pragma unroll
        for (int m = 0; m < 8; ++m) {
            size_t node = (size_t)(node0 + ty * 8 + m);
            float4 o;
            o.x = acc[m][0] + b2v.x;
            o.y = acc[m][1] + b2v.y;
            o.z = acc[m][2] + b2v.z;
            o.w = acc[m][3] + b2v.w;
            ((float4*)out)[node * 32 + tx] = o;
        }
    }
}

// ---------------------------------------------------------------------------
extern "C" void kernel_launch(void* const* d_in, const int* in_sizes, int n_in,
                              void* d_out, int out_size) {
    const float* x          = (const float*)d_in[0];
    const float* edge_attr  = (const float*)d_in[1];
    const int*   edge_index = (const int*)d_in[2];   // int32 (JAX x64 off)
    const float* W1         = (const float*)d_in[3];
    const float* b1         = (const float*)d_in[4];
    const float* W2         = (const float*)d_in[5];
    const float* b2         = (const float*)d_in[6];
    float*       out        = (float*)d_out;

    const int* recv = edge_index + N_EDGES;  // edge_index[1]

    cudaFuncSetAttribute(mlp_kernel,
                         cudaFuncAttributeMaxDynamicSharedMemorySize,
                         196608);

    // zero agg: 25.6M floats = 6.4M float4
    zero_agg_kernel<<<25000, 256>>>();
    // scatter: 800K edges * 32 float4-groups
    scatter_kernel<<<100000, 256>>>(edge_attr, recv);
    // fused MLP: 3125 tiles of 64 nodes
    mlp_kernel<<<3125, 256, 196608>>>(x, W1, b1, W2, b2, out);
}